// round 12
// baseline (speedup 1.0000x reference)
#include <cuda_runtime.h>
#include <math.h>

#define EPSV 1e-5f
#define SLOPE 0.2f
#define BB 4
#define NN 4096
#define KNN 10
#define K1 11
#define NLISTS 8
#define MTOT (BB*NN)

// D=3 path
#define QD3 128
#define ZD3 4

// GEMM tiling
#define GBM 128
#define GBN 128
#define GBK 8

// ---------------- scratch (device globals; no allocation allowed) ----------------
__device__ float g_cat[MTOT*512];
__device__ float g_ya[MTOT*256];
__device__ float g_yc[MTOT*256];
__device__ float g_sq[MTOT];
__device__ int   g_idx[MTOT*KNN];
__device__ float g_pd[(size_t)MTOT*NLISTS*K1];
__device__ int   g_pi[(size_t)MTOT*NLISTS*K1];
__device__ float g_wc[2*256*128];
__device__ float g_pmax[BB*32*1024];
__device__ float g_pool[BB*1024];
__device__ float g_f1[BB*512];
__device__ float g_f2[BB*256];

// ---------------- squared norms ----------------
__global__ void norms_kernel(const float* __restrict__ x, int ld, int D, float* __restrict__ sq) {
    int row  = blockIdx.x * (blockDim.x >> 5) + (threadIdx.x >> 5);
    int lane = threadIdx.x & 31;
    if (row >= MTOT) return;
    const float* xr = x + (size_t)row * ld;
    float s = 0.f;
    for (int d = lane; d < D; d += 32) { float v = xr[d]; s += v * v; }
    #pragma unroll
    for (int o = 16; o; o >>= 1) s += __shfl_xor_sync(0xffffffffu, s, o);
    if (lane == 0) sq[row] = s;
}

// ---------------- kNN specialist for D=3: smem-broadcast scan ----------------
__global__ __launch_bounds__(128) void knn_d3(
    const float* __restrict__ x, const float* __restrict__ sq,
    float* __restrict__ pd, int* __restrict__ pi)
{
    __shared__ float4 cand[NN / ZD3];          // 16 KB
    const int b = blockIdx.y, z = blockIdx.z;
    const int q = blockIdx.x * QD3 + threadIdx.x;
    const int c_base = z * (NN / ZD3);

    for (int j = threadIdx.x; j < NN / ZD3; j += QD3) {
        const float* p = x + (size_t)(b * NN + c_base + j) * 3;
        cand[j] = make_float4(p[0], p[1], p[2], sq[b * NN + c_base + j]);
    }
    __syncthreads();

    const float* qp = x + (size_t)(b * NN + q) * 3;
    const float qx = qp[0], qy = qp[1], qz = qp[2];
    const float qs = sq[b * NN + q];

    float best[K1]; int bidx[K1];
    #pragma unroll
    for (int j = 0; j < K1; j++) { best[j] = 3e38f; bidx[j] = 0x7fffffff; }
    float kth = 3e38f; int kthi = 0x7fffffff;

    for (int j = 0; j < NN / ZD3; j++) {
        float4 c = cand[j];
        float d2 = qs + c.w - 2.f * (qx * c.x + qy * c.y + qz * c.z);
        int m = c_base + j;
        if (m == q) d2 = -3e38f;
        if (d2 < kth || (d2 == kth && m < kthi)) {
            int p = K1 - 1;
            while (p > 0 && (d2 < best[p - 1] ||
                             (d2 == best[p - 1] && m < bidx[p - 1]))) {
                best[p] = best[p - 1]; bidx[p] = bidx[p - 1]; p--;
            }
            best[p] = d2; bidx[p] = m;
            kth = best[K1 - 1]; kthi = bidx[K1 - 1];
        }
    }

    size_t base = ((size_t)(b * NN + q) * NLISTS + z) * K1;
    #pragma unroll
    for (int j = 0; j < K1; j++) { pd[base + j] = best[j]; pi[base + j] = bidx[j]; }
}

// ---------------- kNN (D>=64): thread-per-query, query in registers -------------
// grid (NN/128, BB, ZS), 128 threads. Candidate tile [CBt][D] in dynamic smem;
// scan index j is warp-uniform so candidate LDS.128 are broadcasts. No syncs in
// the scan loop. top-11 arrays are rare-path local-memory (knn_d3 precedent).
// Writes partial list slot z; merge with nl=ZS.
template<int D, int CBt, int ZS>
__global__ __launch_bounds__(128) void knn_reg(
    const float* __restrict__ x, int ld, const float* __restrict__ sq,
    float* __restrict__ pd, int* __restrict__ pi)
{
    static_assert(ZS <= NLISTS, "slots exceed NLISTS");
    extern __shared__ float smem[];
    float* tile = smem;              // [CBt][D]
    float* sqc  = smem + CBt * D;    // [CBt]

    const int b = blockIdx.y, z = blockIdx.z;
    const int q = blockIdx.x * 128 + threadIdx.x;

    float qv[D];
    {
        const float* qp = x + (size_t)(b * NN + q) * ld;
        #pragma unroll
        for (int d = 0; d < D; d += 4) {
            float4 v = *(const float4*)(qp + d);
            qv[d] = v.x; qv[d+1] = v.y; qv[d+2] = v.z; qv[d+3] = v.w;
        }
    }
    const float qs = sq[b * NN + q];

    float best[K1]; int bidx[K1];
    #pragma unroll
    for (int j = 0; j < K1; j++) { best[j] = 3e38f; bidx[j] = 0x7fffffff; }
    float kth = 3e38f; int kthi = 0x7fffffff;

    const int c_begin = z * (NN / ZS);
    for (int c0 = c_begin; c0 < c_begin + NN / ZS; c0 += CBt) {
        __syncthreads();
        for (int e = threadIdx.x; e < CBt * D / 4; e += 128) {
            int r = e / (D / 4), c4 = e % (D / 4);
            *(float4*)(tile + r * D + c4 * 4) =
                *(const float4*)(x + (size_t)(b * NN + c0 + r) * ld + c4 * 4);
        }
        for (int e = threadIdx.x; e < CBt; e += 128) sqc[e] = sq[b * NN + c0 + e];
        __syncthreads();

        #pragma unroll 2
        for (int j = 0; j < CBt; j++) {
            const float* cp = tile + j * D;
            float a0 = 0.f, a1 = 0.f, a2 = 0.f, a3 = 0.f;
            #pragma unroll
            for (int d = 0; d < D; d += 4) {
                float4 c = *(const float4*)(cp + d);
                a0 += qv[d]   * c.x;
                a1 += qv[d+1] * c.y;
                a2 += qv[d+2] * c.z;
                a3 += qv[d+3] * c.w;
            }
            float dot = (a0 + a1) + (a2 + a3);
            float d2 = qs + sqc[j] - 2.f * dot;
            int m = c0 + j;
            if (m == q) d2 = -3e38f;
            if (d2 < kth || (d2 == kth && m < kthi)) {
                int p = K1 - 1;
                while (p > 0 && (d2 < best[p - 1] ||
                                 (d2 == best[p - 1] && m < bidx[p - 1]))) {
                    best[p] = best[p - 1]; bidx[p] = bidx[p - 1]; p--;
                }
                best[p] = d2; bidx[p] = m;
                kth = best[K1 - 1]; kthi = bidx[K1 - 1];
            }
        }
    }

    size_t base = ((size_t)(b * NN + q) * NLISTS + z) * K1;
    #pragma unroll
    for (int j = 0; j < K1; j++) { pd[base + j] = best[j]; pi[base + j] = bidx[j]; }
}

// ---------------- kNN: merge nl partial lists (lexicographic on (d, idx)) ----------
__global__ void knn_merge(const float* __restrict__ pd, const int* __restrict__ pi,
                          int* __restrict__ idx, int nl) {
    int row = blockIdx.x * blockDim.x + threadIdx.x;
    if (row >= MTOT) return;
    float best[K1]; int bidx[K1];
    #pragma unroll
    for (int j = 0; j < K1; j++) { best[j] = 3e38f; bidx[j] = 0x7fffffff; }
    for (int s = 0; s < nl; s++) {
        size_t base = ((size_t)row * NLISTS + s) * K1;
        for (int j = 0; j < K1; j++) {
            float d2 = pd[base + j];
            int m = pi[base + j];
            if (d2 < best[K1 - 1] || (d2 == best[K1 - 1] && m < bidx[K1 - 1])) {
                int p = K1 - 1;
                while (p > 0 && (d2 < best[p - 1] || (d2 == best[p - 1] && m < bidx[p - 1]))) {
                    best[p] = best[p - 1]; bidx[p] = bidx[p - 1]; p--;
                }
                best[p] = d2; bidx[p] = m;
            }
        }
    }
    for (int j = 1; j < K1; j++) idx[row * KNN + (j - 1)] = bidx[j];
}

// ---------------- wc = w[:, D:2D] - w[:, 0:D] ----------------
__global__ void wc_kernel(const float* __restrict__ w, int O, int D, float* __restrict__ out) {
    int e = blockIdx.x * 256 + threadIdx.x;
    if (e < O * D) {
        int o = e / D, d = e % D;
        out[e] = w[o * 2 * D + D + d] - w[o * 2 * D + d];
    }
}

// ---------------- fp32 GEMM: C[M,Nc] = A[M,K] * B[Nc,K]^T (dbuf, 1 sync/kstep) ----
template<int EPI>
__global__ __launch_bounds__(256) void gemm_tn(
    const float* __restrict__ A, int lda,
    const float* __restrict__ Bm, int ldb,
    float* __restrict__ C, int ldc,
    int M, int Nc, int K,
    const float* __restrict__ gam, const float* __restrict__ bet)
{
    __shared__ float As[2][GBK][GBM + 4];
    __shared__ float Bs[2][GBK][GBN + 4];
    const int t = threadIdx.x;
    const int tx = t & 15, ty = t >> 4;
    const int row0 = blockIdx.y * GBM, col0 = blockIdx.x * GBN;
    const int lr = t >> 1, lk = (t & 1) * 4;
    const bool vec = ((K & 7) == 0) && ((lda & 3) == 0) && ((ldb & 3) == 0);
    const bool bvalid = (col0 + lr) < Nc;
    const float* Arow = A + (size_t)(row0 + lr) * lda;
    const float* Brow = Bm + (size_t)(col0 + lr) * ldb;

    float acc[8][8];
    #pragma unroll
    for (int i = 0; i < 8; i++)
        #pragma unroll
        for (int j = 0; j < 8; j++) acc[i][j] = 0.f;

    float4 pa, pb;
    if (vec) {
        pa = *(const float4*)(Arow + lk);
        pb = bvalid ? *(const float4*)(Brow + lk) : make_float4(0.f,0.f,0.f,0.f);
    } else {
        pa.x = (lk+0 < K) ? Arow[lk+0] : 0.f;
        pa.y = (lk+1 < K) ? Arow[lk+1] : 0.f;
        pa.z = (lk+2 < K) ? Arow[lk+2] : 0.f;
        pa.w = (lk+3 < K) ? Arow[lk+3] : 0.f;
        pb.x = (bvalid && lk+0 < K) ? Brow[lk+0] : 0.f;
        pb.y = (bvalid && lk+1 < K) ? Brow[lk+1] : 0.f;
        pb.z = (bvalid && lk+2 < K) ? Brow[lk+2] : 0.f;
        pb.w = (bvalid && lk+3 < K) ? Brow[lk+3] : 0.f;
    }
    As[0][lk+0][lr] = pa.x; As[0][lk+1][lr] = pa.y;
    As[0][lk+2][lr] = pa.z; As[0][lk+3][lr] = pa.w;
    Bs[0][lk+0][lr] = pb.x; Bs[0][lk+1][lr] = pb.y;
    Bs[0][lk+2][lr] = pb.z; Bs[0][lk+3][lr] = pb.w;

    int buf = 0;
    for (int k0 = 0; k0 < K; k0 += GBK) {
        const bool nxt = (k0 + GBK) < K;
        if (nxt) {
            int kn = k0 + GBK + lk;
            if (vec) {
                pa = *(const float4*)(Arow + kn);
                pb = bvalid ? *(const float4*)(Brow + kn) : make_float4(0.f,0.f,0.f,0.f);
            } else {
                pa.x = (kn+0 < K) ? Arow[kn+0] : 0.f;
                pa.y = (kn+1 < K) ? Arow[kn+1] : 0.f;
                pa.z = (kn+2 < K) ? Arow[kn+2] : 0.f;
                pa.w = (kn+3 < K) ? Arow[kn+3] : 0.f;
                pb.x = (bvalid && kn+0 < K) ? Brow[kn+0] : 0.f;
                pb.y = (bvalid && kn+1 < K) ? Brow[kn+1] : 0.f;
                pb.z = (bvalid && kn+2 < K) ? Brow[kn+2] : 0.f;
                pb.w = (bvalid && kn+3 < K) ? Brow[kn+3] : 0.f;
            }
        }
        __syncthreads();
        #pragma unroll
        for (int kk = 0; kk < GBK; kk++) {
            float4 a0 = *(const float4*)(&As[buf][kk][ty * 8]);
            float4 a1 = *(const float4*)(&As[buf][kk][ty * 8 + 4]);
            float4 b0 = *(const float4*)(&Bs[buf][kk][tx * 8]);
            float4 b1 = *(const float4*)(&Bs[buf][kk][tx * 8 + 4]);
            float a[8]  = {a0.x, a0.y, a0.z, a0.w, a1.x, a1.y, a1.z, a1.w};
            float bv[8] = {b0.x, b0.y, b0.z, b0.w, b1.x, b1.y, b1.z, b1.w};
            #pragma unroll
            for (int i = 0; i < 8; i++)
                #pragma unroll
                for (int j = 0; j < 8; j++) acc[i][j] += a[i] * bv[j];
        }
        if (nxt) {
            int nb = buf ^ 1;
            As[nb][lk+0][lr] = pa.x; As[nb][lk+1][lr] = pa.y;
            As[nb][lk+2][lr] = pa.z; As[nb][lk+3][lr] = pa.w;
            Bs[nb][lk+0][lr] = pb.x; Bs[nb][lk+1][lr] = pb.y;
            Bs[nb][lk+2][lr] = pb.z; Bs[nb][lk+3][lr] = pb.w;
        }
        buf ^= 1;
    }

    const float inv = 1.0f / sqrtf(1.0f + EPSV);

    if (EPI == 2) {
        float cmax[8];
        #pragma unroll
        for (int j = 0; j < 8; j++) {
            int c = col0 + tx * 8 + j;
            float sc = gam[c] * inv, bi = bet[c];
            float m = -3e38f;
            #pragma unroll
            for (int i = 0; i < 8; i++) {
                float v = acc[i][j] * sc + bi;
                v = v > 0.f ? v : SLOPE * v;
                m = fmaxf(m, v);
            }
            cmax[j] = m;
        }
        __syncthreads();
        float* red = &As[0][0][0];
        #pragma unroll
        for (int j = 0; j < 8; j++) red[ty * 128 + tx * 8 + j] = cmax[j];
        __syncthreads();
        if (t < 128) {
            float m = red[t];
            #pragma unroll
            for (int g = 1; g < 16; g++) m = fmaxf(m, red[g * 128 + t]);
            C[(size_t)(row0 >> 7) * ldc + col0 + t] = m;
        }
        return;
    }

    #pragma unroll
    for (int j = 0; j < 8; j++) {
        int c = col0 + tx * 8 + j;
        if (c >= Nc) continue;
        float sc = 1.f, bi = 0.f;
        if (EPI == 1) { sc = gam[c] * inv; bi = bet[c]; }
        #pragma unroll
        for (int i = 0; i < 8; i++) {
            int r = row0 + ty * 8 + i;
            float v = acc[i][j];
            if (EPI == 1) { v = v * sc + bi; v = v > 0.f ? v : SLOPE * v; }
            C[(size_t)r * ldc + c] = v;
        }
    }
}

// ---------------- edge aggregate ----------------
__global__ void aggregate_kernel(const float* __restrict__ ya, const float* __restrict__ yc,
                                 const int* __restrict__ idx,
                                 const float* __restrict__ g, const float* __restrict__ bt,
                                 float* __restrict__ out, int O, int col0)
{
    int row = blockIdx.x;
    int b = row / NN;
    int o = threadIdx.x;
    __shared__ int sidx[KNN];
    if (threadIdx.x < KNN) sidx[threadIdx.x] = idx[row * KNN + threadIdx.x];
    __syncthreads();
    float cv = yc[(size_t)row * O + o];
    float sc = g[o] * (1.0f / sqrtf(1.0f + EPSV));
    float bi = bt[o];
    float best = -3e38f;
    #pragma unroll
    for (int j = 0; j < KNN; j++) {
        float v = ya[(size_t)(b * NN + sidx[j]) * O + o] + cv;
        v = v * sc + bi;
        v = v > 0.f ? v : SLOPE * v;
        best = fmaxf(best, v);
    }
    out[(size_t)row * 512 + col0 + o] = best;
}

// ---------------- final reduce over 32 row-chunks ----------------
__global__ void maxpool2(const float* __restrict__ pm, float* __restrict__ out) {
    int b = blockIdx.y;
    int o = blockIdx.x * 256 + threadIdx.x;
    float best = -3e38f;
    for (int s = 0; s < 32; s++)
        best = fmaxf(best, pm[(size_t)(b * 32 + s) * 1024 + o]);
    out[b * 1024 + o] = best;
}

// ---------------- small FC layers ----------------
__global__ void fc_kernel(const float* __restrict__ in, int K,
                          const float* __restrict__ W, const float* __restrict__ b0,
                          const float* __restrict__ g, const float* __restrict__ bt,
                          float* __restrict__ out, int O, int mode)
{
    int wid = (blockIdx.x * blockDim.x + threadIdx.x) >> 5;
    int lane = threadIdx.x & 31;
    if (wid >= BB * O) return;
    int b = wid / O, o = wid % O;
    const float* ir = in + b * K;
    const float* wr = W + (size_t)o * K;
    float s = 0.f;
    for (int c = lane; c < K; c += 32) s += ir[c] * wr[c];
    #pragma unroll
    for (int off = 16; off; off >>= 1) s += __shfl_xor_sync(0xffffffffu, s, off);
    if (lane == 0) {
        if (mode == 2) out[b * O + o] = s + b0[o];
        else {
            if (mode == 1) s += b0[o];
            float v = s * (g[o] * (1.0f / sqrtf(1.0f + EPSV))) + bt[o];
            out[b * O + o] = v > 0.f ? v : SLOPE * v;
        }
    }
}

// ---------------- host orchestration ----------------
static void edge_tail(const float* xin, int ld, int D, int O,
                      const float* w, const float* wcp,
                      const float* g, const float* bt, int col0,
                      float* cat, float* ya, float* yc, int* idx)
{
    dim3 gg((O + GBN - 1) / GBN, MTOT / GBM);
    gemm_tn<0><<<gg, 256>>>(xin, ld, w,   2 * D, ya, O, MTOT, O, D, nullptr, nullptr);
    gemm_tn<0><<<gg, 256>>>(xin, ld, wcp, D,     yc, O, MTOT, O, D, nullptr, nullptr);
    aggregate_kernel<<<MTOT, O>>>(ya, yc, idx, g, bt, cat, O, col0);
}

static void knn64(const float* xin, int ld, const float* sq, float* pd, int* pi) {
    constexpr int CBt = 256, ZS = 4;
    size_t sm = (size_t)(CBt * 64 + CBt) * 4;          // 65 KB
    cudaFuncSetAttribute(knn_reg<64, CBt, ZS>,
                         cudaFuncAttributeMaxDynamicSharedMemorySize, (int)sm);
    knn_reg<64, CBt, ZS><<<dim3(NN / 128, BB, ZS), 128, sm>>>(xin, ld, sq, pd, pi);
}
static void knn128(const float* xin, int ld, const float* sq, float* pd, int* pi) {
    constexpr int CBt = 128, ZS = 4;
    size_t sm = (size_t)(CBt * 128 + CBt) * 4;         // 64.5 KB
    cudaFuncSetAttribute(knn_reg<128, CBt, ZS>,
                         cudaFuncAttributeMaxDynamicSharedMemorySize, (int)sm);
    knn_reg<128, CBt, ZS><<<dim3(NN / 128, BB, ZS), 128, sm>>>(xin, ld, sq, pd, pi);
}

extern "C" void kernel_launch(void* const* d_in, const int* in_sizes, int n_in,
                              void* d_out, int out_size)
{
    const float* T[26]; int ti = 0;
    for (int i = 0; i < n_in && ti < 26; i++) {
        if (in_sizes[i] == 1) continue;
        T[ti++] = (const float*)d_in[i];
    }
    const float* points = T[0];
    const float* w1 = T[1],  *g1 = T[2],  *b1 = T[3];
    const float* w2 = T[4],  *g2 = T[5],  *b2 = T[6];
    const float* w3 = T[7],  *g3 = T[8],  *b3 = T[9];
    const float* w4 = T[10], *g4 = T[11], *b4 = T[12];
    const float* w5 = T[13], *g5 = T[14], *b5 = T[15];
    const float* fw1 = T[16], *fg1 = T[17], *fbt1 = T[18];
    const float* fw2 = T[19], *fb2 = T[20], *fg2 = T[21], *fbt2 = T[22];
    const float* fw3 = T[23], *fb3 = T[24];

    float *cat, *ya, *yc, *sq, *pd, *wc, *pmax, *pool, *f1, *f2;
    int *idx, *pi;
    cudaGetSymbolAddress((void**)&cat,  g_cat);
    cudaGetSymbolAddress((void**)&ya,   g_ya);
    cudaGetSymbolAddress((void**)&yc,   g_yc);
    cudaGetSymbolAddress((void**)&sq,   g_sq);
    cudaGetSymbolAddress((void**)&pd,   g_pd);
    cudaGetSymbolAddress((void**)&pi,   g_pi);
    cudaGetSymbolAddress((void**)&idx,  g_idx);
    cudaGetSymbolAddress((void**)&wc,   g_wc);
    cudaGetSymbolAddress((void**)&pmax, g_pmax);
    cudaGetSymbolAddress((void**)&pool, g_pool);
    cudaGetSymbolAddress((void**)&f1,   g_f1);
    cudaGetSymbolAddress((void**)&f2,   g_f2);

    float* wcA = wc;
    float* wcB = wc + 32768;

    // ---- layer 1: D=3 specialist kNN (slots 0..3) ----
    norms_kernel<<<MTOT / 8, 256>>>(points, 3, 3, sq);
    wc_kernel<<<(64 * 3 + 255) / 256, 256>>>(w1, 64, 3, wcA);
    wc_kernel<<<(64 * 64 + 255) / 256, 256>>>(w2, 64, 64, wcB);
    knn_d3<<<dim3(NN / QD3, BB, ZD3), QD3>>>(points, sq, pd, pi);
    knn_merge<<<(MTOT + 255) / 256, 256>>>(pd, pi, idx, ZD3);
    edge_tail(points, 3, 3, 64, w1, wcA, g1, b1, 0, cat, ya, yc, idx);

    // ---- layer 2 (knn_reg<64>, ZS=4 -> slots 0..3) ----
    norms_kernel<<<MTOT / 8, 256>>>(cat + 0, 512, 64, sq);
    knn64(cat + 0, 512, sq, pd, pi);
    knn_merge<<<(MTOT + 255) / 256, 256>>>(pd, pi, idx, 4);
    edge_tail(cat + 0, 512, 64, 64, w2, wcB, g2, b2, 64, cat, ya, yc, idx);

    // ---- layer 3 ----
    wc_kernel<<<(128 * 64 + 255) / 256, 256>>>(w3, 128, 64, wcA);
    norms_kernel<<<MTOT / 8, 256>>>(cat + 64, 512, 64, sq);
    knn64(cat + 64, 512, sq, pd, pi);
    knn_merge<<<(MTOT + 255) / 256, 256>>>(pd, pi, idx, 4);
    edge_tail(cat + 64, 512, 64, 128, w3, wcA, g3, b3, 128, cat, ya, yc, idx);

    // ---- layer 4 ----
    wc_kernel<<<(256 * 128 + 255) / 256, 256>>>(w4, 256, 128, wcB);
    norms_kernel<<<MTOT / 8, 256>>>(cat + 128, 512, 128, sq);
    knn128(cat + 128, 512, sq, pd, pi);
    knn_merge<<<(MTOT + 255) / 256, 256>>>(pd, pi, idx, 4);
    edge_tail(cat + 128, 512, 128, 256, w4, wcB, g4, b4, 256, cat, ya, yc, idx);

    // ---- w5 GEMM with fused bn+lrelu+max-pool ----
    {
        dim3 gg(1024 / GBN, MTOT / GBM);
        gemm_tn<2><<<gg, 256>>>(cat, 512, w5, 512, pmax, 1024, MTOT, 1024, 512, g5, b5);
    }
    maxpool2<<<dim3(4, BB), 256>>>(pmax, pool);

    // ---- FC head ----
    fc_kernel<<<(BB * 512 * 32 + 255) / 256, 256>>>(pool, 1024, fw1, nullptr, fg1, fbt1, f1, 512, 0);
    fc_kernel<<<(BB * 256 * 32 + 255) / 256, 256>>>(f1, 512, fw2, fb2, fg2, fbt2, f2, 256, 1);
    fc_kernel<<<(BB * 3 * 32 + 255) / 256, 256>>>(f2, 256, fw3, fb3, nullptr, nullptr,
                                                  (float*)d_out, 3, 2);
    (void)out_size;
}

// round 16
// speedup vs baseline: 1.6204x; 1.6204x over previous
#include <cuda_runtime.h>
#include <math.h>

#define EPSV 1e-5f
#define SLOPE 0.2f
#define BB 4
#define NN 4096
#define KNN 10
#define K1 11
#define SSPLIT 4
#define MTOT (BB*NN)

// D=3 specialist
#define QD3 128

// ---------------- scratch (device globals; no allocation allowed) ----------------
__device__ float g_cat[MTOT*512];     // concat of o1..o4 (cols 0:64,64:128,128:256,256:512)
__device__ float g_ya[MTOT*256];
__device__ float g_yc[MTOT*256];
__device__ float g_sq[MTOT];
__device__ int   g_idx[MTOT*KNN];
__device__ float g_pd[(size_t)MTOT*SSPLIT*K1];
__device__ int   g_pi[(size_t)MTOT*SSPLIT*K1];
__device__ float g_wc[256*128];
__device__ float g_pmax[BB*32*1024];
__device__ float g_pool[BB*1024];
__device__ float g_f1[BB*512];
__device__ float g_f2[BB*256];

// ---------------- squared norms ----------------
__global__ void norms_kernel(const float* __restrict__ x, int ld, int D, float* __restrict__ sq) {
    int row  = blockIdx.x * (blockDim.x >> 5) + (threadIdx.x >> 5);
    int lane = threadIdx.x & 31;
    if (row >= MTOT) return;
    const float* xr = x + (size_t)row * ld;
    float s = 0.f;
    for (int d = lane; d < D; d += 32) { float v = xr[d]; s += v * v; }
    #pragma unroll
    for (int o = 16; o; o >>= 1) s += __shfl_xor_sync(0xffffffffu, s, o);
    if (lane == 0) sq[row] = s;
}

// ---------------- kNN specialist for D=3 (validated: ~1.6us/layer) ----------------
// One thread per query; candidates (x,y,z,|c|^2) cached in smem; candidate index
// is warp-uniform so all LDS are broadcasts. Writes partial list slot z of SSPLIT.
__global__ __launch_bounds__(128) void knn_d3(
    const float* __restrict__ x, const float* __restrict__ sq,
    float* __restrict__ pd, int* __restrict__ pi)
{
    __shared__ float4 cand[NN / SSPLIT];          // 16 KB
    const int b = blockIdx.y, z = blockIdx.z;
    const int q = blockIdx.x * QD3 + threadIdx.x;
    const int c_base = z * (NN / SSPLIT);

    for (int j = threadIdx.x; j < NN / SSPLIT; j += QD3) {
        const float* p = x + (size_t)(b * NN + c_base + j) * 3;
        cand[j] = make_float4(p[0], p[1], p[2], sq[b * NN + c_base + j]);
    }
    __syncthreads();

    const float* qp = x + (size_t)(b * NN + q) * 3;
    const float qx = qp[0], qy = qp[1], qz = qp[2];
    const float qs = sq[b * NN + q];

    float best[K1]; int bidx[K1];
    #pragma unroll
    for (int j = 0; j < K1; j++) { best[j] = 3e38f; bidx[j] = 0; }
    float kth = 3e38f;

    for (int j = 0; j < NN / SSPLIT; j++) {
        float4 c = cand[j];
        float d2 = qs + c.w - 2.f * (qx * c.x + qy * c.y + qz * c.z);
        int m = c_base + j;
        if (m == q) d2 = -3e38f;
        if (d2 < kth) {                      // strict <, ascending-m scan: top_k ties
            int p = K1 - 1;
            while (p > 0 && d2 < best[p - 1]) {
                best[p] = best[p - 1]; bidx[p] = bidx[p - 1]; p--;
            }
            best[p] = d2; bidx[p] = m;
            kth = best[K1 - 1];
        }
    }

    size_t base = ((size_t)(b * NN + q) * SSPLIT + z) * K1;
    #pragma unroll
    for (int j = 0; j < K1; j++) { pd[base + j] = best[j]; pi[base + j] = bidx[j]; }
}

// ---------------- kNN: partial top-11 over an m-range (r1-exact, D>=64) ----------
template<int D>
__global__ __launch_bounds__(128) void knn_partial(
    const float* __restrict__ x, int ld, const float* __restrict__ sq,
    float* __restrict__ pd, int* __restrict__ pi)
{
    const int TM = 64;
    __shared__ float tile[TM * D];
    __shared__ float sqs[TM];

    int b = blockIdx.y, z = blockIdx.z;
    int n = blockIdx.x * 128 + threadIdx.x;
    int row = b * NN + n;

    float q[D];
    {
        const float* xr = x + (size_t)row * ld;
        #pragma unroll
        for (int d = 0; d < D; d++) q[d] = xr[d];
    }
    float sqn = sq[row];

    float best[K1]; int bidx[K1];
    #pragma unroll
    for (int j = 0; j < K1; j++) { best[j] = 3e38f; bidx[j] = 0; }
    float kth = 3e38f;

    const int len = NN / SSPLIT;
    const int m0 = z * len;

    for (int t0 = m0; t0 < m0 + len; t0 += TM) {
        __syncthreads();
        {
            const int NF4 = TM * D / 4;
            for (int e = threadIdx.x; e < NF4; e += 128) {
                int mm = e / (D / 4), c4 = e % (D / 4);
                float4 v = *(const float4*)(x + (size_t)(b * NN + t0 + mm) * ld + c4 * 4);
                *(float4*)(tile + mm * D + c4 * 4) = v;
            }
        }
        if (threadIdx.x < TM) sqs[threadIdx.x] = sq[b * NN + t0 + threadIdx.x];
        __syncthreads();

        for (int mm = 0; mm < TM; mm++) {
            float acc = 0.f;
            #pragma unroll
            for (int d = 0; d < D; d += 4) {
                float4 v = *(const float4*)(tile + mm * D + d);
                acc += q[d] * v.x; acc += q[d+1] * v.y;
                acc += q[d+2] * v.z; acc += q[d+3] * v.w;
            }
            int m = t0 + mm;
            float d2 = sqn + sqs[mm] - 2.f * acc;
            if (m == n) d2 = -3e38f;
            if (d2 < kth) {
                int j = K1 - 1;
                while (j > 0 && d2 < best[j - 1]) {
                    best[j] = best[j - 1]; bidx[j] = bidx[j - 1]; j--;
                }
                best[j] = d2; bidx[j] = m;
                kth = best[K1 - 1];
            }
        }
    }
    size_t base = ((size_t)row * SSPLIT + z) * K1;
    for (int j = 0; j < K1; j++) { pd[base + j] = best[j]; pi[base + j] = bidx[j]; }
}

// ---------------- kNN: merge S partial lists (r1-exact) ----------------
__global__ void knn_merge(const float* __restrict__ pd, const int* __restrict__ pi,
                          int* __restrict__ idx) {
    int row = blockIdx.x * blockDim.x + threadIdx.x;
    if (row >= MTOT) return;
    float best[K1]; int bidx[K1];
    #pragma unroll
    for (int j = 0; j < K1; j++) { best[j] = 3e38f; bidx[j] = 0; }
    for (int z = 0; z < SSPLIT; z++) {
        size_t base = ((size_t)row * SSPLIT + z) * K1;
        for (int j = 0; j < K1; j++) {
            float d2 = pd[base + j];
            int m = pi[base + j];
            if (d2 < best[K1 - 1]) {
                int p = K1 - 1;
                while (p > 0 && d2 < best[p - 1]) {
                    best[p] = best[p - 1]; bidx[p] = bidx[p - 1]; p--;
                }
                best[p] = d2; bidx[p] = m;
            }
        }
    }
    for (int j = 1; j < K1; j++) idx[row * KNN + (j - 1)] = bidx[j];
}

// ---------------- wc = w[:, D:2D] - w[:, 0:D] ----------------
__global__ void wc_kernel(const float* __restrict__ w, int O, int D, float* __restrict__ out) {
    int e = blockIdx.x * 256 + threadIdx.x;
    if (e < O * D) {
        int o = e / D, d = e % D;
        out[e] = w[o * 2 * D + D + d] - w[o * 2 * D + d];
    }
}

// ---------------- fp32 GEMM (r1-exact mainloop): C = A[M,K] * B[Nc,K]^T ----------
// EPI 0: raw store. EPI 2: lrelu(bn(acc)) then per-block row-max -> fused pool.
#define GBM 128
#define GBN 128
#define GBK 16
template<int EPI>
__global__ __launch_bounds__(256) void gemm_tn(
    const float* __restrict__ A, int lda,
    const float* __restrict__ Bm, int ldb,
    float* __restrict__ C, int ldc,
    int M, int Nc, int K,
    const float* __restrict__ gam, const float* __restrict__ bet)
{
    __shared__ float As[GBK][GBM + 4];
    __shared__ float Bs[GBK][GBN + 4];
    int t = threadIdx.x;
    int tx = t & 15, ty = t >> 4;        // 16 x 16 threads, 8x8 micro-tile
    int row0 = blockIdx.y * GBM, col0 = blockIdx.x * GBN;

    float acc[8][8];
    #pragma unroll
    for (int i = 0; i < 8; i++)
        #pragma unroll
        for (int j = 0; j < 8; j++) acc[i][j] = 0.f;

    for (int k0 = 0; k0 < K; k0 += GBK) {
        #pragma unroll
        for (int i = 0; i < 8; i++) {
            int e = t + i * 256;
            int r = e >> 4, c = e & 15;
            float v = 0.f;
            if (k0 + c < K) v = A[(size_t)(row0 + r) * lda + k0 + c];
            As[c][r] = v;
        }
        #pragma unroll
        for (int i = 0; i < 8; i++) {
            int e = t + i * 256;
            int r = e >> 4, c = e & 15;
            float v = 0.f;
            if (k0 + c < K && col0 + r < Nc) v = Bm[(size_t)(col0 + r) * ldb + k0 + c];
            Bs[c][r] = v;
        }
        __syncthreads();
        #pragma unroll
        for (int kk = 0; kk < GBK; kk++) {
            float a[8], bv[8];
            #pragma unroll
            for (int i = 0; i < 8; i++) a[i] = As[kk][ty * 8 + i];
            #pragma unroll
            for (int j = 0; j < 8; j++) bv[j] = Bs[kk][tx * 8 + j];
            #pragma unroll
            for (int i = 0; i < 8; i++)
                #pragma unroll
                for (int j = 0; j < 8; j++) acc[i][j] += a[i] * bv[j];
        }
        __syncthreads();
    }

    const float inv = 1.0f / sqrtf(1.0f + EPSV);

    if (EPI == 2) {
        // fused bn + lrelu + block-row max; no C tile store
        float cmax[8];
        #pragma unroll
        for (int j = 0; j < 8; j++) {
            int c = col0 + tx * 8 + j;
            float sc = gam[c] * inv, bi = bet[c];
            float m = -3e38f;
            #pragma unroll
            for (int i = 0; i < 8; i++) {
                float v = acc[i][j] * sc + bi;
                v = v > 0.f ? v : SLOPE * v;
                m = fmaxf(m, v);
            }
            cmax[j] = m;
        }
        __syncthreads();
        float* red = &As[0][0];          // 16*132 floats >= 2048
        #pragma unroll
        for (int j = 0; j < 8; j++) red[ty * 128 + tx * 8 + j] = cmax[j];
        __syncthreads();
        if (t < 128) {
            float m = red[t];
            #pragma unroll
            for (int g = 1; g < 16; g++) m = fmaxf(m, red[g * 128 + t]);
            C[(size_t)(row0 >> 7) * ldc + col0 + t] = m;
        }
        return;
    }

    #pragma unroll
    for (int j = 0; j < 8; j++) {
        int c = col0 + tx * 8 + j;
        if (c >= Nc) continue;
        #pragma unroll
        for (int i = 0; i < 8; i++) {
            int r = row0 + ty * 8 + i;
            C[(size_t)r * ldc + c] = acc[i][j];
        }
    }
}

// ---------------- edge aggregate: gather + add + affine + lrelu + max_k ----------------
__global__ void aggregate_kernel(const float* __restrict__ ya, const float* __restrict__ yc,
                                 const int* __restrict__ idx,
                                 const float* __restrict__ g, const float* __restrict__ bt,
                                 float* __restrict__ out, int O, int col0)
{
    int row = blockIdx.x;
    int b = row / NN;
    int o = threadIdx.x;
    __shared__ int sidx[KNN];
    if (threadIdx.x < KNN) sidx[threadIdx.x] = idx[row * KNN + threadIdx.x];
    __syncthreads();
    float cv = yc[(size_t)row * O + o];
    float sc = g[o] * (1.0f / sqrtf(1.0f + EPSV));
    float bi = bt[o];
    float best = -3e38f;
    #pragma unroll
    for (int j = 0; j < KNN; j++) {
        float v = ya[(size_t)(b * NN + sidx[j]) * O + o] + cv;
        v = v * sc + bi;
        v = v > 0.f ? v : SLOPE * v;
        best = fmaxf(best, v);
    }
    out[(size_t)row * 512 + col0 + o] = best;
}

// ---------------- final reduce over 32 row-chunks ----------------
__global__ void maxpool2(const float* __restrict__ pm, float* __restrict__ out) {
    int b = blockIdx.y;
    int o = blockIdx.x * 256 + threadIdx.x;
    float best = -3e38f;
    for (int s = 0; s < 32; s++)
        best = fmaxf(best, pm[(size_t)(b * 32 + s) * 1024 + o]);
    out[b * 1024 + o] = best;
}

// ---------------- small FC layers (warp per output) ----------------
__global__ void fc_kernel(const float* __restrict__ in, int K,
                          const float* __restrict__ W, const float* __restrict__ b0,
                          const float* __restrict__ g, const float* __restrict__ bt,
                          float* __restrict__ out, int O, int mode)
{
    int wid = (blockIdx.x * blockDim.x + threadIdx.x) >> 5;
    int lane = threadIdx.x & 31;
    if (wid >= BB * O) return;
    int b = wid / O, o = wid % O;
    const float* ir = in + b * K;
    const float* wr = W + (size_t)o * K;
    float s = 0.f;
    for (int c = lane; c < K; c += 32) s += ir[c] * wr[c];
    #pragma unroll
    for (int off = 16; off; off >>= 1) s += __shfl_xor_sync(0xffffffffu, s, off);
    if (lane == 0) {
        if (mode == 2) out[b * O + o] = s + b0[o];
        else {
            if (mode == 1) s += b0[o];
            float v = s * (g[o] * (1.0f / sqrtf(1.0f + EPSV))) + bt[o];
            out[b * O + o] = v > 0.f ? v : SLOPE * v;
        }
    }
}

// ---------------- host orchestration ----------------
static void run_edge_layer(const float* xin, int ld, int D, int O,
                           const float* w, const float* g, const float* bt, int col0,
                           float* cat, float* ya, float* yc, float* sq,
                           float* pd, int* pi, int* idx, float* wc)
{
    norms_kernel<<<MTOT / 8, 256>>>(xin, ld, D, sq);
    if (D == 3) {
        knn_d3<<<dim3(NN / QD3, BB, SSPLIT), QD3>>>(xin, sq, pd, pi);
    } else {
        dim3 kg(NN / 128, BB, SSPLIT);
        if (D == 64) knn_partial<64><<<kg, 128>>>(xin, ld, sq, pd, pi);
        else         knn_partial<128><<<kg, 128>>>(xin, ld, sq, pd, pi);
    }
    knn_merge<<<(MTOT + 255) / 256, 256>>>(pd, pi, idx);

    wc_kernel<<<(O * D + 255) / 256, 256>>>(w, O, D, wc);
    dim3 gg((O + GBN - 1) / GBN, MTOT / GBM);
    gemm_tn<0><<<gg, 256>>>(xin, ld, w,  2 * D, ya, O, MTOT, O, D, nullptr, nullptr);
    gemm_tn<0><<<gg, 256>>>(xin, ld, wc, D,     yc, O, MTOT, O, D, nullptr, nullptr);

    aggregate_kernel<<<MTOT, O>>>(ya, yc, idx, g, bt, cat, O, col0);
}

extern "C" void kernel_launch(void* const* d_in, const int* in_sizes, int n_in,
                              void* d_out, int out_size)
{
    const float* T[26]; int ti = 0;
    for (int i = 0; i < n_in && ti < 26; i++) {
        if (in_sizes[i] == 1) continue;
        T[ti++] = (const float*)d_in[i];
    }
    const float* points = T[0];
    const float* w1 = T[1],  *g1 = T[2],  *b1 = T[3];
    const float* w2 = T[4],  *g2 = T[5],  *b2 = T[6];
    const float* w3 = T[7],  *g3 = T[8],  *b3 = T[9];
    const float* w4 = T[10], *g4 = T[11], *b4 = T[12];
    const float* w5 = T[13], *g5 = T[14], *b5 = T[15];
    const float* fw1 = T[16], *fg1 = T[17], *fbt1 = T[18];
    const float* fw2 = T[19], *fb2 = T[20], *fg2 = T[21], *fbt2 = T[22];
    const float* fw3 = T[23], *fb3 = T[24];

    float *cat, *ya, *yc, *sq, *pd, *wc, *pmax, *pool, *f1, *f2;
    int *idx, *pi;
    cudaGetSymbolAddress((void**)&cat,  g_cat);
    cudaGetSymbolAddress((void**)&ya,   g_ya);
    cudaGetSymbolAddress((void**)&yc,   g_yc);
    cudaGetSymbolAddress((void**)&sq,   g_sq);
    cudaGetSymbolAddress((void**)&pd,   g_pd);
    cudaGetSymbolAddress((void**)&pi,   g_pi);
    cudaGetSymbolAddress((void**)&idx,  g_idx);
    cudaGetSymbolAddress((void**)&wc,   g_wc);
    cudaGetSymbolAddress((void**)&pmax, g_pmax);
    cudaGetSymbolAddress((void**)&pool, g_pool);
    cudaGetSymbolAddress((void**)&f1,   g_f1);
    cudaGetSymbolAddress((void**)&f2,   g_f2);

    // EdgeConv 1..4 (output columns 0,64,128,256 of cat)
    run_edge_layer(points,    3,   3,   64,  w1, g1, b1, 0,   cat, ya, yc, sq, pd, pi, idx, wc);
    run_edge_layer(cat + 0,   512, 64,  64,  w2, g2, b2, 64,  cat, ya, yc, sq, pd, pi, idx, wc);
    run_edge_layer(cat + 64,  512, 64,  128, w3, g3, b3, 128, cat, ya, yc, sq, pd, pi, idx, wc);
    run_edge_layer(cat + 128, 512, 128, 256, w4, g4, b4, 256, cat, ya, yc, sq, pd, pi, idx, wc);

    // w5 GEMM with fused bn+lrelu+max-pool, then final 32-chunk reduce
    {
        dim3 gg(1024 / GBN, MTOT / GBM);
        gemm_tn<2><<<gg, 256>>>(cat, 512, w5, 512, pmax, 1024, MTOT, 1024, 512, g5, b5);
    }
    maxpool2<<<dim3(4, BB), 256>>>(pmax, pool);

    // FC head
    fc_kernel<<<(BB * 512 * 32 + 255) / 256, 256>>>(pool, 1024, fw1, nullptr, fg1, fbt1, f1, 512, 0);
    fc_kernel<<<(BB * 256 * 32 + 255) / 256, 256>>>(f1, 512, fw2, fb2, fg2, fbt2, f2, 256, 1);
    fc_kernel<<<(BB * 3 * 32 + 255) / 256, 256>>>(f2, 256, fw3, fb3, nullptr, nullptr,
                                                  (float*)d_out, 3, 2);
    (void)out_size;
}